// round 11
// baseline (speedup 1.0000x reference)
#include <cuda_runtime.h>
#include <cuda_bf16.h>
#include <cstdint>

#define N_NODES 100000
#define N_EDGES 1600000
#define NFEAT 256
#define NHID 128
#define NCLASS 40
#define SCAN_BS 1024
#define NB ((N_NODES + SCAN_BS - 1) / SCAN_BS)   // 98

// Scratch (device globals — no allocation allowed)
__device__ float g_bufA[(size_t)N_NODES * NHID];   // 51.2 MB
__device__ float g_bufB[(size_t)N_NODES * NHID];   // 51.2 MB
__device__ float g_bufC[(size_t)N_NODES * NCLASS]; // 16 MB
__device__ int   g_deg[N_NODES];
__device__ int   g_off[N_NODES + 1];
__device__ int   g_cursor[N_NODES];
__device__ int   g_bsum[SCAN_BS];
__device__ int2  g_csr[N_EDGES];                   // {src, float bits of val}

// ---------------------------------------------------------------------------
// tf32 helpers
// ---------------------------------------------------------------------------
__device__ __forceinline__ uint32_t f2tf32(float x) {
    uint32_t r;
    asm("cvt.rna.tf32.f32 %0, %1;" : "=r"(r) : "f"(x));
    return r;
}

__device__ __forceinline__ void mma_tf32(float* d, const uint32_t* a, uint32_t b0, uint32_t b1) {
    asm volatile(
        "mma.sync.aligned.m16n8k8.row.col.f32.tf32.tf32.f32 "
        "{%0,%1,%2,%3}, {%4,%5,%6,%7}, {%8,%9}, {%0,%1,%2,%3};"
        : "+f"(d[0]), "+f"(d[1]), "+f"(d[2]), "+f"(d[3])
        : "r"(a[0]), "r"(a[1]), "r"(a[2]), "r"(a[3]), "r"(b0), "r"(b1));
}

// ---------------------------------------------------------------------------
// Tensor-core GEMM (3xTF32, fp32-accurate): C[N, 128] = (relu?)(A)[N, FIN] @ W
// ---------------------------------------------------------------------------
#define KB 16
#define SA_STRIDE 20
#define SW_STRIDE 136

template<int FIN, bool RELU>
__global__ __launch_bounds__(256, 2)
void gemm_tc_kernel(const float* __restrict__ A,
                    const float* __restrict__ W,
                    float* __restrict__ C) {
    __shared__ uint32_t sAh[128 * SA_STRIDE];
    __shared__ uint32_t sAl[128 * SA_STRIDE];
    __shared__ uint32_t sWh[KB * SW_STRIDE];
    __shared__ uint32_t sWl[KB * SW_STRIDE];

    const int tid  = threadIdx.x;
    const int lane = tid & 31;
    const int warp = tid >> 5;
    const int wm   = warp & 3;
    const int wn   = warp >> 2;
    const int g    = lane >> 2;
    const int tig  = lane & 3;
    const int row0 = blockIdx.x * 128;

    float acc[2][8][4];
    #pragma unroll
    for (int mf = 0; mf < 2; mf++)
        #pragma unroll
        for (int nf = 0; nf < 8; nf++)
            #pragma unroll
            for (int r = 0; r < 4; r++) acc[mf][nf][r] = 0.f;

    constexpr int NCHUNK = FIN / KB;
    for (int kc = 0; kc < NCHUNK; kc++) {
        #pragma unroll
        for (int j = 0; j < 2; j++) {
            const int fi  = tid * 2 + j;
            const int r   = fi >> 2;
            const int c4  = (fi & 3) * 4;
            const int gr  = min(row0 + r, N_NODES - 1);
            float4 v = __ldg(reinterpret_cast<const float4*>(A + (size_t)gr * FIN + kc * KB + c4));
            if (RELU) {
                v.x = fmaxf(v.x, 0.f); v.y = fmaxf(v.y, 0.f);
                v.z = fmaxf(v.z, 0.f); v.w = fmaxf(v.w, 0.f);
            }
            uint32_t* ph = sAh + r * SA_STRIDE + c4;
            uint32_t* pl = sAl + r * SA_STRIDE + c4;
            const float e[4] = {v.x, v.y, v.z, v.w};
            #pragma unroll
            for (int q = 0; q < 4; q++) {
                const uint32_t hb = f2tf32(e[q]);
                ph[q] = hb;
                pl[q] = f2tf32(e[q] - __uint_as_float(hb));
            }
        }
        #pragma unroll
        for (int j = 0; j < 2; j++) {
            const int fi = tid * 2 + j;
            const int kr = fi >> 5;
            const int c4 = (fi & 31) * 4;
            float4 v = __ldg(reinterpret_cast<const float4*>(W + (size_t)(kc * KB + kr) * 128 + c4));
            uint32_t* ph = sWh + kr * SW_STRIDE + c4;
            uint32_t* pl = sWl + kr * SW_STRIDE + c4;
            const float e[4] = {v.x, v.y, v.z, v.w};
            #pragma unroll
            for (int q = 0; q < 4; q++) {
                const uint32_t hb = f2tf32(e[q]);
                ph[q] = hb;
                pl[q] = f2tf32(e[q] - __uint_as_float(hb));
            }
        }
        __syncthreads();

        #pragma unroll
        for (int ks = 0; ks < 2; ks++) {
            const int k0 = ks * 8;
            uint32_t ah[2][4], al[2][4];
            #pragma unroll
            for (int mf = 0; mf < 2; mf++) {
                const int rbase = wm * 32 + mf * 16 + g;
                ah[mf][0] = sAh[(rbase)     * SA_STRIDE + k0 + tig];
                ah[mf][1] = sAh[(rbase + 8) * SA_STRIDE + k0 + tig];
                ah[mf][2] = sAh[(rbase)     * SA_STRIDE + k0 + tig + 4];
                ah[mf][3] = sAh[(rbase + 8) * SA_STRIDE + k0 + tig + 4];
                al[mf][0] = sAl[(rbase)     * SA_STRIDE + k0 + tig];
                al[mf][1] = sAl[(rbase + 8) * SA_STRIDE + k0 + tig];
                al[mf][2] = sAl[(rbase)     * SA_STRIDE + k0 + tig + 4];
                al[mf][3] = sAl[(rbase + 8) * SA_STRIDE + k0 + tig + 4];
            }
            #pragma unroll
            for (int nf = 0; nf < 8; nf++) {
                const int col = wn * 64 + nf * 8 + g;
                const uint32_t bh0 = sWh[(k0 + tig)     * SW_STRIDE + col];
                const uint32_t bh1 = sWh[(k0 + tig + 4) * SW_STRIDE + col];
                const uint32_t bl0 = sWl[(k0 + tig)     * SW_STRIDE + col];
                const uint32_t bl1 = sWl[(k0 + tig + 4) * SW_STRIDE + col];
                #pragma unroll
                for (int mf = 0; mf < 2; mf++) {
                    mma_tf32(acc[mf][nf], ah[mf], bh0, bh1);
                    mma_tf32(acc[mf][nf], ah[mf], bl0, bl1);
                    mma_tf32(acc[mf][nf], al[mf], bh0, bh1);
                }
            }
        }
        __syncthreads();
    }

    #pragma unroll
    for (int mf = 0; mf < 2; mf++) {
        const int r0 = row0 + wm * 32 + mf * 16 + g;
        const int r1 = r0 + 8;
        #pragma unroll
        for (int nf = 0; nf < 8; nf++) {
            const int c = wn * 64 + nf * 8 + tig * 2;
            if (r0 < N_NODES)
                *reinterpret_cast<float2*>(C + (size_t)r0 * 128 + c) =
                    make_float2(acc[mf][nf][0], acc[mf][nf][1]);
            if (r1 < N_NODES)
                *reinterpret_cast<float2*>(C + (size_t)r1 * 128 + c) =
                    make_float2(acc[mf][nf][2], acc[mf][nf][3]);
        }
    }
}

// ---------------------------------------------------------------------------
// Small GEMM for layer 3 (FOUT=40), fused ReLU on A.
// ---------------------------------------------------------------------------
template<int FIN, int FOUT, int G, int TR, bool RELU>
__global__ void gemm_small_kernel(const float* __restrict__ A,
                                  const float* __restrict__ W,
                                  float* __restrict__ C) {
    constexpr int BM = G * TR;
    constexpr int NT = FOUT * G;
    __shared__ float sA[BM * FIN];

    const int col  = threadIdx.x;
    const int g    = threadIdx.y;
    const int row0 = blockIdx.x * BM;
    const int tid  = threadIdx.y * FOUT + threadIdx.x;

    const float4* A4  = reinterpret_cast<const float4*>(A + (size_t)row0 * FIN);
    float4*       sA4 = reinterpret_cast<float4*>(sA);
    constexpr int NV = BM * FIN / 4;
    for (int i = tid; i < NV; i += NT) {
        float4 v = __ldg(A4 + i);
        if (RELU) {
            v.x = fmaxf(v.x, 0.f); v.y = fmaxf(v.y, 0.f);
            v.z = fmaxf(v.z, 0.f); v.w = fmaxf(v.w, 0.f);
        }
        sA4[i] = v;
    }
    __syncthreads();

    float acc[TR];
    #pragma unroll
    for (int r = 0; r < TR; r++) acc[r] = 0.f;

    #pragma unroll 4
    for (int k = 0; k < FIN; k++) {
        const float w = __ldg(W + (size_t)k * FOUT + col);
        #pragma unroll
        for (int r = 0; r < TR; r++)
            acc[r] += sA[(g * TR + r) * FIN + k] * w;
    }

    #pragma unroll
    for (int r = 0; r < TR; r++)
        C[(size_t)(row0 + g * TR + r) * FOUT + col] = acc[r];
}

// ---------------------------------------------------------------------------
// CSR build: histogram -> shuffle scans -> fill (packed int2)
// ---------------------------------------------------------------------------
__global__ void hist_kernel(const int* __restrict__ dst, int* __restrict__ deg) {
    const int e = blockIdx.x * blockDim.x + threadIdx.x;
    if (e < N_EDGES) atomicAdd(deg + __ldg(dst + e), 1);
}

__global__ void scan_block_kernel(const int* __restrict__ deg,
                                  int* __restrict__ off,
                                  int* __restrict__ bsum) {
    __shared__ int wsum[32];
    const int tid  = threadIdx.x;
    const int lane = tid & 31;
    const int wid  = tid >> 5;
    const int i    = blockIdx.x * SCAN_BS + tid;
    const int v    = (i < N_NODES) ? deg[i] : 0;

    int s = v;
    #pragma unroll
    for (int o = 1; o < 32; o <<= 1) {
        const int n = __shfl_up_sync(0xffffffffu, s, o);
        if (lane >= o) s += n;
    }
    if (lane == 31) wsum[wid] = s;
    __syncthreads();
    if (wid == 0) {
        int ws = wsum[lane];
        #pragma unroll
        for (int o = 1; o < 32; o <<= 1) {
            const int n = __shfl_up_sync(0xffffffffu, ws, o);
            if (lane >= o) ws += n;
        }
        wsum[lane] = ws;
    }
    __syncthreads();
    const int incl = s + (wid ? wsum[wid - 1] : 0);
    if (i < N_NODES) off[i] = incl - v;
    if (tid == SCAN_BS - 1) bsum[blockIdx.x] = incl;
}

__global__ void scan_sums_kernel(int* __restrict__ bsum) {
    __shared__ int wsum[4];
    const int tid  = threadIdx.x;      // 128 threads, NB=98 live
    const int lane = tid & 31;
    const int wid  = tid >> 5;
    const int v = (tid < NB) ? bsum[tid] : 0;
    int s = v;
    #pragma unroll
    for (int o = 1; o < 32; o <<= 1) {
        const int n = __shfl_up_sync(0xffffffffu, s, o);
        if (lane >= o) s += n;
    }
    if (lane == 31) wsum[wid] = s;
    __syncthreads();
    int add = 0;
    for (int w = 0; w < wid; w++) add += wsum[w];
    if (tid < NB) bsum[tid] = s + add - v;   // exclusive
}

// Finalize offsets AND initialize the fill cursor (folds the old memcpy).
__global__ void scan_add2_kernel(int* __restrict__ off,
                                 int* __restrict__ cursor,
                                 const int* __restrict__ bsum) {
    const int i = blockIdx.x * blockDim.x + threadIdx.x;
    if (i < N_NODES) {
        const int v = off[i] + __ldg(bsum + (i / SCAN_BS));
        off[i] = v;
        cursor[i] = v;
    }
    if (i == 0) off[N_NODES] = N_EDGES;
}

__global__ void csr_fill_kernel(const int* __restrict__ src,
                                const int* __restrict__ dst,
                                const float* __restrict__ ev,
                                int* __restrict__ cursor,
                                int2* __restrict__ csr) {
    const int e = blockIdx.x * blockDim.x + threadIdx.x;
    if (e >= N_EDGES) return;
    const int d = __ldg(dst + e);
    const int p = atomicAdd(cursor + d, 1);
    csr[p] = make_int2(__ldg(src + e), __float_as_int(__ldg(ev + e)));
}

// ---------------------------------------------------------------------------
// Slab pull-mode aggregation, 64 features per pass (L2-resident read slab).
// Warp per node; lane = (edge parity h = lane>>4, float4 column c = lane&15).
// Both half-warps walk the edge list two-at-a-time; shfl_xor(16) reduction.
// ---------------------------------------------------------------------------
__global__ void gather_slab_kernel(const float* __restrict__ S,
                                   const int* __restrict__ off,
                                   const int2* __restrict__ csr,
                                   const float* __restrict__ bias,
                                   float* __restrict__ agg,
                                   const int slab) {
    const int warp = threadIdx.x >> 5;
    const int lane = threadIdx.x & 31;
    const int d    = blockIdx.x * 8 + warp;
    if (d >= N_NODES) return;
    const int c = lane & 15;
    const int h = lane >> 4;
    const int beg = __ldg(off + d);
    const int end = __ldg(off + d + 1);
    const int base4 = slab * 16 + c;               // float4 column index in row
    const float4* S4 = reinterpret_cast<const float4*>(S);

    float ax, ay, az, aw;
    if (h == 0) {
        const float4 b = __ldg(reinterpret_cast<const float4*>(bias) + base4);
        ax = b.x; ay = b.y; az = b.z; aw = b.w;
    } else {
        ax = ay = az = aw = 0.f;
    }

    int i = beg;
    for (; i + 8 <= end; i += 8) {                 // 4 pairs -> 4 rows per half-warp
        int2 e[4];
        #pragma unroll
        for (int j = 0; j < 4; j++) e[j] = __ldg(csr + i + 2 * j + h);
        float4 x[4];
        #pragma unroll
        for (int j = 0; j < 4; j++)
            x[j] = __ldcg(S4 + (size_t)e[j].x * 32 + base4);
        #pragma unroll
        for (int j = 0; j < 4; j++) {
            const float v = __int_as_float(e[j].y);
            ax += v * x[j].x; ay += v * x[j].y;
            az += v * x[j].z; aw += v * x[j].w;
        }
    }
    for (; i + 2 <= end; i += 2) {
        const int2 e = __ldg(csr + i + h);
        const float v = __int_as_float(e.y);
        const float4 x = __ldcg(S4 + (size_t)e.x * 32 + base4);
        ax += v * x.x; ay += v * x.y; az += v * x.z; aw += v * x.w;
    }
    if (i + h < end) {                             // odd tail: only h==0 live
        const int2 e = __ldg(csr + i + h);
        const float v = __int_as_float(e.y);
        const float4 x = __ldcg(S4 + (size_t)e.x * 32 + base4);
        ax += v * x.x; ay += v * x.y; az += v * x.z; aw += v * x.w;
    }

    ax += __shfl_xor_sync(0xffffffffu, ax, 16);
    ay += __shfl_xor_sync(0xffffffffu, ay, 16);
    az += __shfl_xor_sync(0xffffffffu, az, 16);
    aw += __shfl_xor_sync(0xffffffffu, aw, 16);
    if (h == 0)
        reinterpret_cast<float4*>(agg)[(size_t)d * 32 + base4] =
            make_float4(ax, ay, az, aw);
}

// ---------------------------------------------------------------------------
// Pull-mode aggregation, F = 40: block of 64 (40 active) per node, unroll 8.
// ---------------------------------------------------------------------------
__global__ void gather40_kernel(const float* __restrict__ S,
                                const int* __restrict__ off,
                                const int2* __restrict__ csr,
                                const float* __restrict__ bias,
                                float* __restrict__ agg) {
    const int d = blockIdx.x;
    const int t = threadIdx.x;
    if (t >= NCLASS) return;
    const int beg = __ldg(off + d);
    const int end = __ldg(off + d + 1);
    float acc = __ldg(bias + t);
    int i = beg;
    for (; i + 8 <= end; i += 8) {
        int2 e[8];
        #pragma unroll
        for (int j = 0; j < 8; j++) e[j] = __ldg(csr + i + j);
        float x[8];
        #pragma unroll
        for (int j = 0; j < 8; j++)
            x[j] = __ldcg(S + (size_t)e[j].x * NCLASS + t);
        #pragma unroll
        for (int j = 0; j < 8; j++)
            acc += __int_as_float(e[j].y) * x[j];
    }
    for (; i < end; i++) {
        const int2 e = __ldg(csr + i);
        acc += __int_as_float(e.y) * __ldcg(S + (size_t)e.x * NCLASS + t);
    }
    agg[(size_t)d * NCLASS + t] = acc;
}

// ---------------------------------------------------------------------------
// In-place log_softmax over 40 classes: warp per row.
// ---------------------------------------------------------------------------
__global__ void logsoftmax_kernel(float* __restrict__ out) {
    const int warp = threadIdx.x >> 5;
    const int lane = threadIdx.x & 31;
    const int row  = blockIdx.x * 8 + warp;
    if (row >= N_NODES) return;
    float* p = out + (size_t)row * NCLASS;

    const float NEG_INF = __int_as_float(0xff800000);
    float v0 = p[lane];
    float v1 = (lane < 8) ? p[32 + lane] : NEG_INF;

    float m = fmaxf(v0, v1);
    #pragma unroll
    for (int o = 16; o; o >>= 1) m = fmaxf(m, __shfl_xor_sync(0xffffffffu, m, o));

    float s = expf(v0 - m) + ((lane < 8) ? expf(v1 - m) : 0.f);
    #pragma unroll
    for (int o = 16; o; o >>= 1) s += __shfl_xor_sync(0xffffffffu, s, o);

    const float ls = m + logf(s);
    p[lane] = v0 - ls;
    if (lane < 8) p[32 + lane] = v1 - ls;
}

// ---------------------------------------------------------------------------
extern "C" void kernel_launch(void* const* d_in, const int* in_sizes, int n_in,
                              void* d_out, int out_size) {
    const float* x    = (const float*)d_in[0];
    const int*   esrc = (const int*)  d_in[1];
    const int*   edst = (const int*)  d_in[2];
    const float* ev   = (const float*)d_in[3];
    const float* W1   = (const float*)d_in[4];
    const float* b1   = (const float*)d_in[5];
    const float* W2   = (const float*)d_in[6];
    const float* b2   = (const float*)d_in[7];
    const float* W3   = (const float*)d_in[8];
    const float* b3   = (const float*)d_in[9];
    float* out = (float*)d_out;

    float *bufA, *bufB, *bufC;
    int *deg, *off, *cursor, *bsum;
    int2 *csr;
    cudaGetSymbolAddress((void**)&bufA,   g_bufA);
    cudaGetSymbolAddress((void**)&bufB,   g_bufB);
    cudaGetSymbolAddress((void**)&bufC,   g_bufC);
    cudaGetSymbolAddress((void**)&deg,    g_deg);
    cudaGetSymbolAddress((void**)&off,    g_off);
    cudaGetSymbolAddress((void**)&cursor, g_cursor);
    cudaGetSymbolAddress((void**)&bsum,   g_bsum);
    cudaGetSymbolAddress((void**)&csr,    g_csr);

    const int edge_blocks   = (N_EDGES + 255) / 256;
    const int gemm_blocks   = (N_NODES + 127) / 128;
    const int gather_blocks = (N_NODES + 7) / 8;

    // ---- Build CSR by destination (reused by all 3 layers) ----
    cudaMemsetAsync(deg, 0, N_NODES * sizeof(int));
    hist_kernel<<<edge_blocks, 256>>>(edst, deg);
    scan_block_kernel<<<NB, SCAN_BS>>>(deg, off, bsum);
    scan_sums_kernel<<<1, 128>>>(bsum);
    scan_add2_kernel<<<(N_NODES + 255) / 256, 256>>>(off, cursor, bsum);
    csr_fill_kernel<<<edge_blocks, 256>>>(esrc, edst, ev, cursor, csr);

    // ---- Layer 1 ----
    gemm_tc_kernel<NFEAT, false><<<gemm_blocks, 256>>>(x, W1, bufA);
    gather_slab_kernel<<<gather_blocks, 256>>>(bufA, off, csr, b1, bufB, 0);
    gather_slab_kernel<<<gather_blocks, 256>>>(bufA, off, csr, b1, bufB, 1);

    // ---- Layer 2 ----
    gemm_tc_kernel<NHID, true><<<gemm_blocks, 256>>>(bufB, W2, bufA);
    gather_slab_kernel<<<gather_blocks, 256>>>(bufA, off, csr, b2, bufB, 0);
    gather_slab_kernel<<<gather_blocks, 256>>>(bufA, off, csr, b2, bufB, 1);

    // ---- Layer 3 ----
    gemm_small_kernel<NHID, NCLASS, 8, 2, true><<<N_NODES / 16, dim3(NCLASS, 8)>>>(bufB, W3, bufC);
    gather40_kernel<<<N_NODES, 64>>>(bufC, off, csr, b3, out);
    logsoftmax_kernel<<<(N_NODES + 7) / 8, 256>>>(out);
}

// round 13
// speedup vs baseline: 1.1592x; 1.1592x over previous
#include <cuda_runtime.h>
#include <cuda_fp16.h>
#include <cstdint>

#define N_NODES 100000
#define N_EDGES 1600000
#define NFEAT 256
#define NHID 128
#define NCLASS 40
#define SCAN_BS 1024
#define NB ((N_NODES + SCAN_BS - 1) / SCAN_BS)   // 98

// Scratch (device globals — no allocation allowed)
__device__ float g_bufA[(size_t)N_NODES * NHID];   // 51.2 MB (fp16 support lives here)
__device__ float g_bufB[(size_t)N_NODES * NHID];   // 51.2 MB (fp32 agg)
__device__ float g_bufC[(size_t)N_NODES * NCLASS]; // 16 MB
__device__ int   g_deg[N_NODES];
__device__ int   g_off[N_NODES + 1];
__device__ int   g_cursor[N_NODES];
__device__ int   g_bsum[SCAN_BS];
__device__ int2  g_csr[N_EDGES];                   // {src, float bits of val}

// ---------------------------------------------------------------------------
// tf32 helpers
// ---------------------------------------------------------------------------
__device__ __forceinline__ uint32_t f2tf32(float x) {
    uint32_t r;
    asm("cvt.rna.tf32.f32 %0, %1;" : "=r"(r) : "f"(x));
    return r;
}

__device__ __forceinline__ void mma_tf32(float* d, const uint32_t* a, uint32_t b0, uint32_t b1) {
    asm volatile(
        "mma.sync.aligned.m16n8k8.row.col.f32.tf32.tf32.f32 "
        "{%0,%1,%2,%3}, {%4,%5,%6,%7}, {%8,%9}, {%0,%1,%2,%3};"
        : "+f"(d[0]), "+f"(d[1]), "+f"(d[2]), "+f"(d[3])
        : "r"(a[0]), "r"(a[1]), "r"(a[2]), "r"(a[3]), "r"(b0), "r"(b1));
}

// ---------------------------------------------------------------------------
// Tensor-core GEMM (3xTF32): C[N, 128] = (relu?)(A)[N, FIN] @ W, fp16 output.
// ---------------------------------------------------------------------------
#define KB 16
#define SA_STRIDE 20
#define SW_STRIDE 136

template<int FIN, bool RELU>
__global__ __launch_bounds__(256, 2)
void gemm_tc_kernel(const float* __restrict__ A,
                    const float* __restrict__ W,
                    __half* __restrict__ C) {
    __shared__ uint32_t sAh[128 * SA_STRIDE];
    __shared__ uint32_t sAl[128 * SA_STRIDE];
    __shared__ uint32_t sWh[KB * SW_STRIDE];
    __shared__ uint32_t sWl[KB * SW_STRIDE];

    const int tid  = threadIdx.x;
    const int lane = tid & 31;
    const int warp = tid >> 5;
    const int wm   = warp & 3;
    const int wn   = warp >> 2;
    const int g    = lane >> 2;
    const int tig  = lane & 3;
    const int row0 = blockIdx.x * 128;

    float acc[2][8][4];
    #pragma unroll
    for (int mf = 0; mf < 2; mf++)
        #pragma unroll
        for (int nf = 0; nf < 8; nf++)
            #pragma unroll
            for (int r = 0; r < 4; r++) acc[mf][nf][r] = 0.f;

    constexpr int NCHUNK = FIN / KB;
    for (int kc = 0; kc < NCHUNK; kc++) {
        #pragma unroll
        for (int j = 0; j < 2; j++) {
            const int fi  = tid * 2 + j;
            const int r   = fi >> 2;
            const int c4  = (fi & 3) * 4;
            const int gr  = min(row0 + r, N_NODES - 1);
            float4 v = __ldg(reinterpret_cast<const float4*>(A + (size_t)gr * FIN + kc * KB + c4));
            if (RELU) {
                v.x = fmaxf(v.x, 0.f); v.y = fmaxf(v.y, 0.f);
                v.z = fmaxf(v.z, 0.f); v.w = fmaxf(v.w, 0.f);
            }
            uint32_t* ph = sAh + r * SA_STRIDE + c4;
            uint32_t* pl = sAl + r * SA_STRIDE + c4;
            const float e[4] = {v.x, v.y, v.z, v.w};
            #pragma unroll
            for (int q = 0; q < 4; q++) {
                const uint32_t hb = f2tf32(e[q]);
                ph[q] = hb;
                pl[q] = f2tf32(e[q] - __uint_as_float(hb));
            }
        }
        #pragma unroll
        for (int j = 0; j < 2; j++) {
            const int fi = tid * 2 + j;
            const int kr = fi >> 5;
            const int c4 = (fi & 31) * 4;
            float4 v = __ldg(reinterpret_cast<const float4*>(W + (size_t)(kc * KB + kr) * 128 + c4));
            uint32_t* ph = sWh + kr * SW_STRIDE + c4;
            uint32_t* pl = sWl + kr * SW_STRIDE + c4;
            const float e[4] = {v.x, v.y, v.z, v.w};
            #pragma unroll
            for (int q = 0; q < 4; q++) {
                const uint32_t hb = f2tf32(e[q]);
                ph[q] = hb;
                pl[q] = f2tf32(e[q] - __uint_as_float(hb));
            }
        }
        __syncthreads();

        #pragma unroll
        for (int ks = 0; ks < 2; ks++) {
            const int k0 = ks * 8;
            uint32_t ah[2][4], al[2][4];
            #pragma unroll
            for (int mf = 0; mf < 2; mf++) {
                const int rbase = wm * 32 + mf * 16 + g;
                ah[mf][0] = sAh[(rbase)     * SA_STRIDE + k0 + tig];
                ah[mf][1] = sAh[(rbase + 8) * SA_STRIDE + k0 + tig];
                ah[mf][2] = sAh[(rbase)     * SA_STRIDE + k0 + tig + 4];
                ah[mf][3] = sAh[(rbase + 8) * SA_STRIDE + k0 + tig + 4];
                al[mf][0] = sAl[(rbase)     * SA_STRIDE + k0 + tig];
                al[mf][1] = sAl[(rbase + 8) * SA_STRIDE + k0 + tig];
                al[mf][2] = sAl[(rbase)     * SA_STRIDE + k0 + tig + 4];
                al[mf][3] = sAl[(rbase + 8) * SA_STRIDE + k0 + tig + 4];
            }
            #pragma unroll
            for (int nf = 0; nf < 8; nf++) {
                const int col = wn * 64 + nf * 8 + g;
                const uint32_t bh0 = sWh[(k0 + tig)     * SW_STRIDE + col];
                const uint32_t bh1 = sWh[(k0 + tig + 4) * SW_STRIDE + col];
                const uint32_t bl0 = sWl[(k0 + tig)     * SW_STRIDE + col];
                const uint32_t bl1 = sWl[(k0 + tig + 4) * SW_STRIDE + col];
                #pragma unroll
                for (int mf = 0; mf < 2; mf++) {
                    mma_tf32(acc[mf][nf], ah[mf], bh0, bh1);
                    mma_tf32(acc[mf][nf], ah[mf], bl0, bl1);
                    mma_tf32(acc[mf][nf], al[mf], bh0, bh1);
                }
            }
        }
        __syncthreads();
    }

    // epilogue: half2 stores
    #pragma unroll
    for (int mf = 0; mf < 2; mf++) {
        const int r0 = row0 + wm * 32 + mf * 16 + g;
        const int r1 = r0 + 8;
        #pragma unroll
        for (int nf = 0; nf < 8; nf++) {
            const int c = wn * 64 + nf * 8 + tig * 2;
            if (r0 < N_NODES)
                *reinterpret_cast<__half2*>(C + (size_t)r0 * 128 + c) =
                    __floats2half2_rn(acc[mf][nf][0], acc[mf][nf][1]);
            if (r1 < N_NODES)
                *reinterpret_cast<__half2*>(C + (size_t)r1 * 128 + c) =
                    __floats2half2_rn(acc[mf][nf][2], acc[mf][nf][3]);
        }
    }
}

// ---------------------------------------------------------------------------
// Small GEMM for layer 3 (FOUT=40), fused ReLU on A, fp32 throughout.
// ---------------------------------------------------------------------------
template<int FIN, int FOUT, int G, int TR, bool RELU>
__global__ void gemm_small_kernel(const float* __restrict__ A,
                                  const float* __restrict__ W,
                                  float* __restrict__ C) {
    constexpr int BM = G * TR;
    constexpr int NT = FOUT * G;
    __shared__ float sA[BM * FIN];

    const int col  = threadIdx.x;
    const int g    = threadIdx.y;
    const int row0 = blockIdx.x * BM;
    const int tid  = threadIdx.y * FOUT + threadIdx.x;

    const float4* A4  = reinterpret_cast<const float4*>(A + (size_t)row0 * FIN);
    float4*       sA4 = reinterpret_cast<float4*>(sA);
    constexpr int NV = BM * FIN / 4;
    for (int i = tid; i < NV; i += NT) {
        float4 v = __ldg(A4 + i);
        if (RELU) {
            v.x = fmaxf(v.x, 0.f); v.y = fmaxf(v.y, 0.f);
            v.z = fmaxf(v.z, 0.f); v.w = fmaxf(v.w, 0.f);
        }
        sA4[i] = v;
    }
    __syncthreads();

    float acc[TR];
    #pragma unroll
    for (int r = 0; r < TR; r++) acc[r] = 0.f;

    #pragma unroll 4
    for (int k = 0; k < FIN; k++) {
        const float w = __ldg(W + (size_t)k * FOUT + col);
        #pragma unroll
        for (int r = 0; r < TR; r++)
            acc[r] += sA[(g * TR + r) * FIN + k] * w;
    }

    #pragma unroll
    for (int r = 0; r < TR; r++)
        C[(size_t)(row0 + g * TR + r) * FOUT + col] = acc[r];
}

// ---------------------------------------------------------------------------
// CSR build: histogram -> shuffle scans -> fill (packed int2)
// ---------------------------------------------------------------------------
__global__ void hist_kernel(const int* __restrict__ dst, int* __restrict__ deg) {
    const int e = blockIdx.x * blockDim.x + threadIdx.x;
    if (e < N_EDGES) atomicAdd(deg + __ldg(dst + e), 1);
}

__global__ void scan_block_kernel(const int* __restrict__ deg,
                                  int* __restrict__ off,
                                  int* __restrict__ bsum) {
    __shared__ int wsum[32];
    const int tid  = threadIdx.x;
    const int lane = tid & 31;
    const int wid  = tid >> 5;
    const int i    = blockIdx.x * SCAN_BS + tid;
    const int v    = (i < N_NODES) ? deg[i] : 0;

    int s = v;
    #pragma unroll
    for (int o = 1; o < 32; o <<= 1) {
        const int n = __shfl_up_sync(0xffffffffu, s, o);
        if (lane >= o) s += n;
    }
    if (lane == 31) wsum[wid] = s;
    __syncthreads();
    if (wid == 0) {
        int ws = wsum[lane];
        #pragma unroll
        for (int o = 1; o < 32; o <<= 1) {
            const int n = __shfl_up_sync(0xffffffffu, ws, o);
            if (lane >= o) ws += n;
        }
        wsum[lane] = ws;
    }
    __syncthreads();
    const int incl = s + (wid ? wsum[wid - 1] : 0);
    if (i < N_NODES) off[i] = incl - v;
    if (tid == SCAN_BS - 1) bsum[blockIdx.x] = incl;
}

__global__ void scan_sums_kernel(int* __restrict__ bsum) {
    __shared__ int wsum[4];
    const int tid  = threadIdx.x;      // 128 threads, NB=98 live
    const int lane = tid & 31;
    const int wid  = tid >> 5;
    const int v = (tid < NB) ? bsum[tid] : 0;
    int s = v;
    #pragma unroll
    for (int o = 1; o < 32; o <<= 1) {
        const int n = __shfl_up_sync(0xffffffffu, s, o);
        if (lane >= o) s += n;
    }
    if (lane == 31) wsum[wid] = s;
    __syncthreads();
    int add = 0;
    for (int w = 0; w < wid; w++) add += wsum[w];
    if (tid < NB) bsum[tid] = s + add - v;   // exclusive
}

// Finalize offsets AND initialize the fill cursor.
__global__ void scan_add2_kernel(int* __restrict__ off,
                                 int* __restrict__ cursor,
                                 const int* __restrict__ bsum) {
    const int i = blockIdx.x * blockDim.x + threadIdx.x;
    if (i < N_NODES) {
        const int v = off[i] + __ldg(bsum + (i / SCAN_BS));
        off[i] = v;
        cursor[i] = v;
    }
    if (i == 0) off[N_NODES] = N_EDGES;
}

__global__ void csr_fill_kernel(const int* __restrict__ src,
                                const int* __restrict__ dst,
                                const float* __restrict__ ev,
                                int* __restrict__ cursor,
                                int2* __restrict__ csr) {
    const int e = blockIdx.x * blockDim.x + threadIdx.x;
    if (e >= N_EDGES) return;
    const int d = __ldg(dst + e);
    const int p = atomicAdd(cursor + d, 1);
    csr[p] = make_int2(__ldg(src + e), __float_as_int(__ldg(ev + e)));
}

// ---------------------------------------------------------------------------
// Pull-mode aggregation, fp16 support rows (256B), fp32 accumulate/output.
// Warp per node; lane owns 4 features (uint2 = 2 x half2), unroll 8.
// ---------------------------------------------------------------------------
__global__ void gather128h_kernel(const __half* __restrict__ S,
                                  const int* __restrict__ off,
                                  const int2* __restrict__ csr,
                                  const float* __restrict__ bias,
                                  float* __restrict__ agg) {
    const int warp = threadIdx.x >> 5;
    const int lane = threadIdx.x & 31;
    const int d    = blockIdx.x * 8 + warp;
    if (d >= N_NODES) return;
    const int beg = __ldg(off + d);
    const int end = __ldg(off + d + 1);

    const uint2* S2 = reinterpret_cast<const uint2*>(S);   // row = 32 uint2
    float4 b = __ldg(reinterpret_cast<const float4*>(bias) + lane);
    float ax = b.x, ay = b.y, az = b.z, aw = b.w;

    int i = beg;
    for (; i + 8 <= end; i += 8) {
        int2 e[8];
        #pragma unroll
        for (int j = 0; j < 8; j++) e[j] = __ldg(csr + i + j);
        uint2 x[8];
        #pragma unroll
        for (int j = 0; j < 8; j++)
            x[j] = __ldcg(S2 + (size_t)e[j].x * 32 + lane);
        #pragma unroll
        for (int j = 0; j < 8; j++) {
            const float v = __int_as_float(e[j].y);
            const float2 f0 = __half22float2(*reinterpret_cast<const __half2*>(&x[j].x));
            const float2 f1 = __half22float2(*reinterpret_cast<const __half2*>(&x[j].y));
            ax += v * f0.x; ay += v * f0.y;
            az += v * f1.x; aw += v * f1.y;
        }
    }
    for (; i < end; i++) {
        const int2 e = __ldg(csr + i);
        const float v = __int_as_float(e.y);
        const uint2 x = __ldcg(S2 + (size_t)e.x * 32 + lane);
        const float2 f0 = __half22float2(*reinterpret_cast<const __half2*>(&x.x));
        const float2 f1 = __half22float2(*reinterpret_cast<const __half2*>(&x.y));
        ax += v * f0.x; ay += v * f0.y;
        az += v * f1.x; aw += v * f1.y;
    }
    reinterpret_cast<float4*>(agg)[(size_t)d * 32 + lane] = make_float4(ax, ay, az, aw);
}

// ---------------------------------------------------------------------------
// Pull-mode aggregation, F = 40 fp32: block of 64 (40 active) per node.
// ---------------------------------------------------------------------------
__global__ void gather40_kernel(const float* __restrict__ S,
                                const int* __restrict__ off,
                                const int2* __restrict__ csr,
                                const float* __restrict__ bias,
                                float* __restrict__ agg) {
    const int d = blockIdx.x;
    const int t = threadIdx.x;
    if (t >= NCLASS) return;
    const int beg = __ldg(off + d);
    const int end = __ldg(off + d + 1);
    float acc = __ldg(bias + t);
    int i = beg;
    for (; i + 8 <= end; i += 8) {
        int2 e[8];
        #pragma unroll
        for (int j = 0; j < 8; j++) e[j] = __ldg(csr + i + j);
        float x[8];
        #pragma unroll
        for (int j = 0; j < 8; j++)
            x[j] = __ldcg(S + (size_t)e[j].x * NCLASS + t);
        #pragma unroll
        for (int j = 0; j < 8; j++)
            acc += __int_as_float(e[j].y) * x[j];
    }
    for (; i < end; i++) {
        const int2 e = __ldg(csr + i);
        acc += __int_as_float(e.y) * __ldcg(S + (size_t)e.x * NCLASS + t);
    }
    agg[(size_t)d * NCLASS + t] = acc;
}

// ---------------------------------------------------------------------------
// In-place log_softmax over 40 classes: warp per row.
// ---------------------------------------------------------------------------
__global__ void logsoftmax_kernel(float* __restrict__ out) {
    const int warp = threadIdx.x >> 5;
    const int lane = threadIdx.x & 31;
    const int row  = blockIdx.x * 8 + warp;
    if (row >= N_NODES) return;
    float* p = out + (size_t)row * NCLASS;

    const float NEG_INF = __int_as_float(0xff800000);
    float v0 = p[lane];
    float v1 = (lane < 8) ? p[32 + lane] : NEG_INF;

    float m = fmaxf(v0, v1);
    #pragma unroll
    for (int o = 16; o; o >>= 1) m = fmaxf(m, __shfl_xor_sync(0xffffffffu, m, o));

    float s = expf(v0 - m) + ((lane < 8) ? expf(v1 - m) : 0.f);
    #pragma unroll
    for (int o = 16; o; o >>= 1) s += __shfl_xor_sync(0xffffffffu, s, o);

    const float ls = m + logf(s);
    p[lane] = v0 - ls;
    if (lane < 8) p[32 + lane] = v1 - ls;
}

// ---------------------------------------------------------------------------
extern "C" void kernel_launch(void* const* d_in, const int* in_sizes, int n_in,
                              void* d_out, int out_size) {
    const float* x    = (const float*)d_in[0];
    const int*   esrc = (const int*)  d_in[1];
    const int*   edst = (const int*)  d_in[2];
    const float* ev   = (const float*)d_in[3];
    const float* W1   = (const float*)d_in[4];
    const float* b1   = (const float*)d_in[5];
    const float* W2   = (const float*)d_in[6];
    const float* b2   = (const float*)d_in[7];
    const float* W3   = (const float*)d_in[8];
    const float* b3   = (const float*)d_in[9];
    float* out = (float*)d_out;

    float *bufA, *bufB, *bufC;
    int *deg, *off, *cursor, *bsum;
    int2 *csr;
    cudaGetSymbolAddress((void**)&bufA,   g_bufA);
    cudaGetSymbolAddress((void**)&bufB,   g_bufB);
    cudaGetSymbolAddress((void**)&bufC,   g_bufC);
    cudaGetSymbolAddress((void**)&deg,    g_deg);
    cudaGetSymbolAddress((void**)&off,    g_off);
    cudaGetSymbolAddress((void**)&cursor, g_cursor);
    cudaGetSymbolAddress((void**)&bsum,   g_bsum);
    cudaGetSymbolAddress((void**)&csr,    g_csr);
    __half* bufAh = reinterpret_cast<__half*>(bufA);

    const int edge_blocks   = (N_EDGES + 255) / 256;
    const int gemm_blocks   = (N_NODES + 127) / 128;
    const int gather_blocks = (N_NODES + 7) / 8;

    // ---- Build CSR by destination (reused by all 3 layers) ----
    cudaMemsetAsync(deg, 0, N_NODES * sizeof(int));
    hist_kernel<<<edge_blocks, 256>>>(edst, deg);
    scan_block_kernel<<<NB, SCAN_BS>>>(deg, off, bsum);
    scan_sums_kernel<<<1, 128>>>(bsum);
    scan_add2_kernel<<<(N_NODES + 255) / 256, 256>>>(off, cursor, bsum);
    csr_fill_kernel<<<edge_blocks, 256>>>(esrc, edst, ev, cursor, csr);

    // ---- Layer 1 ----
    gemm_tc_kernel<NFEAT, false><<<gemm_blocks, 256>>>(x, W1, bufAh);
    gather128h_kernel<<<gather_blocks, 256>>>(bufAh, off, csr, b1, bufB);

    // ---- Layer 2 ----
    gemm_tc_kernel<NHID, true><<<gemm_blocks, 256>>>(bufB, W2, bufAh);
    gather128h_kernel<<<gather_blocks, 256>>>(bufAh, off, csr, b2, bufB);

    // ---- Layer 3 (fp32 path) ----
    gemm_small_kernel<NHID, NCLASS, 8, 2, true><<<N_NODES / 16, dim3(NCLASS, 8)>>>(bufB, W3, bufC);
    gather40_kernel<<<N_NODES, 64>>>(bufC, off, csr, b3, out);
    logsoftmax_kernel<<<(N_NODES + 7) / 8, 256>>>(out);
}

// round 16
// speedup vs baseline: 1.6678x; 1.4388x over previous
#include <cuda_runtime.h>
#include <cuda_fp16.h>
#include <cstdint>

#define N_NODES 100000
#define N_EDGES 1600000
#define NFEAT 256
#define NHID 128
#define NCLASS 40
#define SCAN_BS 1024
#define NB ((N_NODES + SCAN_BS - 1) / SCAN_BS)   // 98

// Scratch (device globals — no allocation allowed)
__device__ float g_bufA[(size_t)N_NODES * NHID];   // fp16 support lives here
__device__ float g_bufB[(size_t)N_NODES * NHID];   // fp32 agg
__device__ float g_bufC[(size_t)N_NODES * NCLASS];
__device__ int   g_deg[N_NODES];
__device__ int   g_off[N_NODES + 1];
__device__ int   g_cursor[N_NODES];
__device__ int   g_bsum[SCAN_BS];
__device__ int2  g_csr[N_EDGES];                   // {src, float bits of val}

// ---------------------------------------------------------------------------
// fp16 hi/lo split helpers
// ---------------------------------------------------------------------------
__device__ __forceinline__ uint32_t pack_split(float a, float b, uint32_t& lo) {
    const __half ha = __float2half_rn(a), hb = __float2half_rn(b);
    const __half la = __float2half_rn(a - __half2float(ha));
    const __half lb = __float2half_rn(b - __half2float(hb));
    const __half2 h = __halves2half2(ha, hb), l = __halves2half2(la, lb);
    lo = *reinterpret_cast<const uint32_t*>(&l);
    return *reinterpret_cast<const uint32_t*>(&h);
}

__device__ __forceinline__ void mma_f16(float* d, const uint32_t* a, uint32_t b0, uint32_t b1) {
    asm volatile(
        "mma.sync.aligned.m16n8k16.row.col.f32.f16.f16.f32 "
        "{%0,%1,%2,%3}, {%4,%5,%6,%7}, {%8,%9}, {%0,%1,%2,%3};"
        : "+f"(d[0]), "+f"(d[1]), "+f"(d[2]), "+f"(d[3])
        : "r"(a[0]), "r"(a[1]), "r"(a[2]), "r"(a[3]), "r"(b0), "r"(b1));
}

// ---------------------------------------------------------------------------
// Tensor-core GEMM (3-term fp16 split, fp32 accum): C[N,128] = (relu?)(A) @ W
// CTA 128x128, 8 warps (4M x 2N), warp tile 32x64, k-chunk 32 (2 x k16 steps).
// SMEM holds half2 pairs packed along k.
// ---------------------------------------------------------------------------
#define SA_ST 20     // half2 units per row (16 used + pad)
#define SW_ST 136    // half2 units per k-pair row (128 used + pad)

template<int FIN, bool RELU>
__global__ __launch_bounds__(256, 2)
void gemm_hmma_kernel(const float* __restrict__ A,
                      const float* __restrict__ W,
                      __half* __restrict__ C) {
    __shared__ uint32_t sAh[128 * SA_ST];
    __shared__ uint32_t sAl[128 * SA_ST];
    __shared__ uint32_t sWh[16 * SW_ST];
    __shared__ uint32_t sWl[16 * SW_ST];

    const int tid  = threadIdx.x;
    const int lane = tid & 31;
    const int warp = tid >> 5;
    const int wm   = warp & 3;
    const int wn   = warp >> 2;
    const int g    = lane >> 2;
    const int tig  = lane & 3;
    const int row0 = blockIdx.x * 128;

    float acc[2][8][4];
    #pragma unroll
    for (int mf = 0; mf < 2; mf++)
        #pragma unroll
        for (int nf = 0; nf < 8; nf++)
            #pragma unroll
            for (int r = 0; r < 4; r++) acc[mf][nf][r] = 0.f;

    constexpr int NCHUNK = FIN / 32;
    for (int kc = 0; kc < NCHUNK; kc++) {
        // ---- A chunk: 128 rows x 32 cols = 1024 float4, 4 per thread ----
        #pragma unroll
        for (int j = 0; j < 4; j++) {
            const int idx = tid + 256 * j;
            const int r   = idx >> 3;
            const int c4  = (idx & 7) * 4;           // k offset within chunk
            const int p0  = (idx & 7) * 2;           // half2 pair index
            const int gr  = min(row0 + r, N_NODES - 1);
            float4 v = __ldg(reinterpret_cast<const float4*>(A + (size_t)gr * FIN + kc * 32 + c4));
            if (RELU) {
                v.x = fmaxf(v.x, 0.f); v.y = fmaxf(v.y, 0.f);
                v.z = fmaxf(v.z, 0.f); v.w = fmaxf(v.w, 0.f);
            }
            uint32_t l0, l1;
            const uint32_t h0 = pack_split(v.x, v.y, l0);
            const uint32_t h1 = pack_split(v.z, v.w, l1);
            *reinterpret_cast<uint2*>(sAh + r * SA_ST + p0) = make_uint2(h0, h1);
            *reinterpret_cast<uint2*>(sAl + r * SA_ST + p0) = make_uint2(l0, l1);
        }
        // ---- W chunk: 32 k-rows x 128 cols; pack half2 along k ----
        // unit = (pair p, colpair cp): read W[2p][2cp..2cp+1], W[2p+1][...]
        #pragma unroll
        for (int j = 0; j < 4; j++) {
            const int idx = tid + 256 * j;           // 0..1023
            const int p   = idx >> 6;                // 0..15
            const int c   = (idx & 63) * 2;          // 0..126
            const float2 v0 = __ldg(reinterpret_cast<const float2*>(W + (size_t)(kc * 32 + 2 * p) * 128 + c));
            const float2 v1 = __ldg(reinterpret_cast<const float2*>(W + (size_t)(kc * 32 + 2 * p + 1) * 128 + c));
            uint32_t l0, l1;
            const uint32_t h0 = pack_split(v0.x, v1.x, l0);  // col c,   k=2p,2p+1
            const uint32_t h1 = pack_split(v0.y, v1.y, l1);  // col c+1
            *reinterpret_cast<uint2*>(sWh + p * SW_ST + c) = make_uint2(h0, h1);
            *reinterpret_cast<uint2*>(sWl + p * SW_ST + c) = make_uint2(l0, l1);
        }
        __syncthreads();

        // ---- 2 k16 steps ----
        #pragma unroll
        for (int ks = 0; ks < 2; ks++) {
            const int pb = ks * 8;
            uint32_t ah[2][4], al[2][4];
            #pragma unroll
            for (int mf = 0; mf < 2; mf++) {
                const int rb = wm * 32 + mf * 16 + g;
                ah[mf][0] = sAh[(rb)     * SA_ST + pb + tig];
                ah[mf][1] = sAh[(rb + 8) * SA_ST + pb + tig];
                ah[mf][2] = sAh[(rb)     * SA_ST + pb + tig + 4];
                ah[mf][3] = sAh[(rb + 8) * SA_ST + pb + tig + 4];
                al[mf][0] = sAl[(rb)     * SA_ST + pb + tig];
                al[mf][1] = sAl[(rb + 8) * SA_ST + pb + tig];
                al[mf][2] = sAl[(rb)     * SA_ST + pb + tig + 4];
                al[mf][3] = sAl[(rb + 8) * SA_ST + pb + tig + 4];
            }
            #pragma unroll
            for (int nf = 0; nf < 8; nf++) {
                const int col = wn * 64 + nf * 8 + g;
                const uint32_t bh0 = sWh[(pb + tig)     * SW_ST + col];
                const uint32_t bh1 = sWh[(pb + tig + 4) * SW_ST + col];
                const uint32_t bl0 = sWl[(pb + tig)     * SW_ST + col];
                const uint32_t bl1 = sWl[(pb + tig + 4) * SW_ST + col];
                #pragma unroll
                for (int mf = 0; mf < 2; mf++) {
                    mma_f16(acc[mf][nf], ah[mf], bh0, bh1);  // hi*hi
                    mma_f16(acc[mf][nf], ah[mf], bl0, bl1);  // hi*lo
                    mma_f16(acc[mf][nf], al[mf], bh0, bh1);  // lo*hi
                }
            }
        }
        __syncthreads();
    }

    // epilogue: half2 stores (C layout identical to tf32 version)
    #pragma unroll
    for (int mf = 0; mf < 2; mf++) {
        const int r0 = row0 + wm * 32 + mf * 16 + g;
        const int r1 = r0 + 8;
        #pragma unroll
        for (int nf = 0; nf < 8; nf++) {
            const int c = wn * 64 + nf * 8 + tig * 2;
            if (r0 < N_NODES)
                *reinterpret_cast<__half2*>(C + (size_t)r0 * 128 + c) =
                    __floats2half2_rn(acc[mf][nf][0], acc[mf][nf][1]);
            if (r1 < N_NODES)
                *reinterpret_cast<__half2*>(C + (size_t)r1 * 128 + c) =
                    __floats2half2_rn(acc[mf][nf][2], acc[mf][nf][3]);
        }
    }
}

// ---------------------------------------------------------------------------
// Small GEMM for layer 3 (FOUT=40), fused ReLU on A, fp32 throughout.
// ---------------------------------------------------------------------------
template<int FIN, int FOUT, int G, int TR, bool RELU>
__global__ void gemm_small_kernel(const float* __restrict__ A,
                                  const float* __restrict__ W,
                                  float* __restrict__ C) {
    constexpr int BM = G * TR;
    constexpr int NT = FOUT * G;
    __shared__ float sA[BM * FIN];

    const int col  = threadIdx.x;
    const int g    = threadIdx.y;
    const int row0 = blockIdx.x * BM;
    const int tid  = threadIdx.y * FOUT + threadIdx.x;

    const float4* A4  = reinterpret_cast<const float4*>(A + (size_t)row0 * FIN);
    float4*       sA4 = reinterpret_cast<float4*>(sA);
    constexpr int NV = BM * FIN / 4;
    for (int i = tid; i < NV; i += NT) {
        float4 v = __ldg(A4 + i);
        if (RELU) {
            v.x = fmaxf(v.x, 0.f); v.y = fmaxf(v.y, 0.f);
            v.z = fmaxf(v.z, 0.f); v.w = fmaxf(v.w, 0.f);
        }
        sA4[i] = v;
    }
    __syncthreads();

    float acc[TR];
    #pragma unroll
    for (int r = 0; r < TR; r++) acc[r] = 0.f;

    #pragma unroll 4
    for (int k = 0; k < FIN; k++) {
        const float w = __ldg(W + (size_t)k * FOUT + col);
        #pragma unroll
        for (int r = 0; r < TR; r++)
            acc[r] += sA[(g * TR + r) * FIN + k] * w;
    }

    #pragma unroll
    for (int r = 0; r < TR; r++)
        C[(size_t)(row0 + g * TR + r) * FOUT + col] = acc[r];
}

// ---------------------------------------------------------------------------
// CSR build: histogram -> shuffle scans -> fill (packed int2)
// ---------------------------------------------------------------------------
__global__ void hist_kernel(const int* __restrict__ dst, int* __restrict__ deg) {
    const int e = blockIdx.x * blockDim.x + threadIdx.x;
    if (e < N_EDGES) atomicAdd(deg + __ldg(dst + e), 1);
}

__global__ void scan_block_kernel(const int* __restrict__ deg,
                                  int* __restrict__ off,
                                  int* __restrict__ bsum) {
    __shared__ int wsum[32];
    const int tid  = threadIdx.x;
    const int lane = tid & 31;
    const int wid  = tid >> 5;
    const int i    = blockIdx.x * SCAN_BS + tid;
    const int v    = (i < N_NODES) ? deg[i] : 0;

    int s = v;
    #pragma unroll
    for (int o = 1; o < 32; o <<= 1) {
        const int n = __shfl_up_sync(0xffffffffu, s, o);
        if (lane >= o) s += n;
    }
    if (lane == 31) wsum[wid] = s;
    __syncthreads();
    if (wid == 0) {
        int ws = wsum[lane];
        #pragma unroll
        for (int o = 1; o < 32; o <<= 1) {
            const int n = __shfl_up_sync(0xffffffffu, ws, o);
            if (lane >= o) ws += n;
        }
        wsum[lane] = ws;
    }
    __syncthreads();
    const int incl = s + (wid ? wsum[wid - 1] : 0);
    if (i < N_NODES) off[i] = incl - v;
    if (tid == SCAN_BS - 1) bsum[blockIdx.x] = incl;
}

__global__ void scan_sums_kernel(int* __restrict__ bsum) {
    __shared__ int wsum[4];
    const int tid  = threadIdx.x;      // 128 threads, NB=98 live
    const int lane = tid & 31;
    const int wid  = tid >> 5;
    const int v = (tid < NB) ? bsum[tid] : 0;
    int s = v;
    #pragma unroll
    for (int o = 1; o < 32; o <<= 1) {
        const int n = __shfl_up_sync(0xffffffffu, s, o);
        if (lane >= o) s += n;
    }
    if (lane == 31) wsum[wid] = s;
    __syncthreads();
    int add = 0;
    for (int w = 0; w < wid; w++) add += wsum[w];
    if (tid < NB) bsum[tid] = s + add - v;   // exclusive
}

__global__ void scan_add2_kernel(int* __restrict__ off,
                                 int* __restrict__ cursor,
                                 const int* __restrict__ bsum) {
    const int i = blockIdx.x * blockDim.x + threadIdx.x;
    if (i < N_NODES) {
        const int v = off[i] + __ldg(bsum + (i / SCAN_BS));
        off[i] = v;
        cursor[i] = v;
    }
    if (i == 0) off[N_NODES] = N_EDGES;
}

__global__ void csr_fill_kernel(const int* __restrict__ src,
                                const int* __restrict__ dst,
                                const float* __restrict__ ev,
                                int* __restrict__ cursor,
                                int2* __restrict__ csr) {
    const int e = blockIdx.x * blockDim.x + threadIdx.x;
    if (e >= N_EDGES) return;
    const int d = __ldg(dst + e);
    const int p = atomicAdd(cursor + d, 1);
    csr[p] = make_int2(__ldg(src + e), __float_as_int(__ldg(ev + e)));
}

// ---------------------------------------------------------------------------
// Pull-mode aggregation, fp16 support rows (256B), fp32 accumulate/output.
// ---------------------------------------------------------------------------
__global__ void gather128h_kernel(const __half* __restrict__ S,
                                  const int* __restrict__ off,
                                  const int2* __restrict__ csr,
                                  const float* __restrict__ bias,
                                  float* __restrict__ agg) {
    const int warp = threadIdx.x >> 5;
    const int lane = threadIdx.x & 31;
    const int d    = blockIdx.x * 8 + warp;
    if (d >= N_NODES) return;
    const int beg = __ldg(off + d);
    const int end = __ldg(off + d + 1);

    const uint2* S2 = reinterpret_cast<const uint2*>(S);
    float4 b = __ldg(reinterpret_cast<const float4*>(bias) + lane);
    float ax = b.x, ay = b.y, az = b.z, aw = b.w;

    int i = beg;
    for (; i + 8 <= end; i += 8) {
        int2 e[8];
        #pragma unroll
        for (int j = 0; j < 8; j++) e[j] = __ldg(csr + i + j);
        uint2 x[8];
        #pragma unroll
        for (int j = 0; j < 8; j++)
            x[j] = __ldcg(S2 + (size_t)e[j].x * 32 + lane);
        #pragma unroll
        for (int j = 0; j < 8; j++) {
            const float v = __int_as_float(e[j].y);
            const float2 f0 = __half22float2(*reinterpret_cast<const __half2*>(&x[j].x));
            const float2 f1 = __half22float2(*reinterpret_cast<const __half2*>(&x[j].y));
            ax += v * f0.x; ay += v * f0.y;
            az += v * f1.x; aw += v * f1.y;
        }
    }
    for (; i < end; i++) {
        const int2 e = __ldg(csr + i);
        const float v = __int_as_float(e.y);
        const uint2 x = __ldcg(S2 + (size_t)e.x * 32 + lane);
        const float2 f0 = __half22float2(*reinterpret_cast<const __half2*>(&x.x));
        const float2 f1 = __half22float2(*reinterpret_cast<const __half2*>(&x.y));
        ax += v * f0.x; ay += v * f0.y;
        az += v * f1.x; aw += v * f1.y;
    }
    reinterpret_cast<float4*>(agg)[(size_t)d * 32 + lane] = make_float4(ax, ay, az, aw);
}

// ---------------------------------------------------------------------------
// Fused gather (F=40) + log_softmax: one block (64 thr) per node.
// ---------------------------------------------------------------------------
__global__ void gather40_softmax_kernel(const float* __restrict__ S,
                                        const int* __restrict__ off,
                                        const int2* __restrict__ csr,
                                        const float* __restrict__ bias,
                                        float* __restrict__ out) {
    const int d = blockIdx.x;
    const int t = threadIdx.x;
    const float NEG_INF = __int_as_float(0xff800000);
    __shared__ float red[64];

    float acc = 0.f;
    if (t < NCLASS) {
        const int beg = __ldg(off + d);
        const int end = __ldg(off + d + 1);
        acc = __ldg(bias + t);
        int i = beg;
        for (; i + 8 <= end; i += 8) {
            int2 e[8];
            #pragma unroll
            for (int j = 0; j < 8; j++) e[j] = __ldg(csr + i + j);
            float x[8];
            #pragma unroll
            for (int j = 0; j < 8; j++)
                x[j] = __ldcg(S + (size_t)e[j].x * NCLASS + t);
            #pragma unroll
            for (int j = 0; j < 8; j++)
                acc += __int_as_float(e[j].y) * x[j];
        }
        for (; i < end; i++) {
            const int2 e = __ldg(csr + i);
            acc += __int_as_float(e.y) * __ldcg(S + (size_t)e.x * NCLASS + t);
        }
    }

    // block max
    red[t] = (t < NCLASS) ? acc : NEG_INF;
    __syncthreads();
    if (t < 32) {
        float x = fmaxf(red[t], red[t + 32]);
        #pragma unroll
        for (int o = 16; o; o >>= 1) x = fmaxf(x, __shfl_xor_sync(0xffffffffu, x, o));
        if (t == 0) red[0] = x;
    }
    __syncthreads();
    const float m = red[0];
    __syncthreads();

    // block sum of exp
    red[t] = (t < NCLASS) ? expf(acc - m) : 0.f;
    __syncthreads();
    if (t < 32) {
        float x = red[t] + red[t + 32];
        #pragma unroll
        for (int o = 16; o; o >>= 1) x += __shfl_xor_sync(0xffffffffu, x, o);
        if (t == 0) red[0] = x;
    }
    __syncthreads();
    const float ls = m + logf(red[0]);

    if (t < NCLASS) out[(size_t)d * NCLASS + t] = acc - ls;
}

// ---------------------------------------------------------------------------
extern "C" void kernel_launch(void* const* d_in, const int* in_sizes, int n_in,
                              void* d_out, int out_size) {
    const float* x    = (const float*)d_in[0];
    const int*   esrc = (const int*)  d_in[1];
    const int*   edst = (const int*)  d_in[2];
    const float* ev   = (const float*)d_in[3];
    const float* W1   = (const float*)d_in[4];
    const float* b1   = (const float*)d_in[5];
    const float* W2   = (const float*)d_in[6];
    const float* b2   = (const float*)d_in[7];
    const float* W3   = (const float*)d_in[8];
    const float* b3   = (const float*)d_in[9];
    float* out = (float*)d_out;

    float *bufA, *bufB, *bufC;
    int *deg, *off, *cursor, *bsum;
    int2 *csr;
    cudaGetSymbolAddress((void**)&bufA,   g_bufA);
    cudaGetSymbolAddress((void**)&bufB,   g_bufB);
    cudaGetSymbolAddress((void**)&bufC,   g_bufC);
    cudaGetSymbolAddress((void**)&deg,    g_deg);
    cudaGetSymbolAddress((void**)&off,    g_off);
    cudaGetSymbolAddress((void**)&cursor, g_cursor);
    cudaGetSymbolAddress((void**)&bsum,   g_bsum);
    cudaGetSymbolAddress((void**)&csr,    g_csr);
    __half* bufAh = reinterpret_cast<__half*>(bufA);

    const int edge_blocks   = (N_EDGES + 255) / 256;
    const int gemm_blocks   = (N_NODES + 127) / 128;
    const int gather_blocks = (N_NODES + 7) / 8;

    // ---- Build CSR by destination (reused by all 3 layers) ----
    cudaMemsetAsync(deg, 0, N_NODES * sizeof(int));
    hist_kernel<<<edge_blocks, 256>>>(edst, deg);
    scan_block_kernel<<<NB, SCAN_BS>>>(deg, off, bsum);
    scan_sums_kernel<<<1, 128>>>(bsum);
    scan_add2_kernel<<<(N_NODES + 255) / 256, 256>>>(off, cursor, bsum);
    csr_fill_kernel<<<edge_blocks, 256>>>(esrc, edst, ev, cursor, csr);

    // ---- Layer 1 ----
    gemm_hmma_kernel<NFEAT, false><<<gemm_blocks, 256>>>(x, W1, bufAh);
    gather128h_kernel<<<gather_blocks, 256>>>(bufAh, off, csr, b1, bufB);

    // ---- Layer 2 ----
    gemm_hmma_kernel<NHID, true><<<gemm_blocks, 256>>>(bufB, W2, bufAh);
    gather128h_kernel<<<gather_blocks, 256>>>(bufAh, off, csr, b2, bufB);

    // ---- Layer 3 (fp32 path, fused softmax) ----
    gemm_small_kernel<NHID, NCLASS, 8, 2, true><<<N_NODES / 16, dim3(NCLASS, 8)>>>(bufB, W3, bufC);
    gather40_softmax_kernel<<<N_NODES, 64>>>(bufC, off, csr, b3, out);
}

// round 17
// speedup vs baseline: 1.7600x; 1.0553x over previous
#include <cuda_runtime.h>
#include <cuda_fp16.h>
#include <cstdint>

#define N_NODES 100000
#define N_EDGES 1600000
#define NFEAT 256
#define NHID 128
#define NCLASS 40
#define SCAN_BS 1024
#define NB ((N_NODES + SCAN_BS - 1) / SCAN_BS)   // 98

// Scratch (device globals — no allocation allowed)
__device__ float g_bufA[(size_t)N_NODES * NHID];   // fp16 support lives here
__device__ float g_bufB[(size_t)N_NODES * NHID];   // fp32 agg
__device__ float g_bufC[(size_t)N_NODES * NCLASS]; // fp16 support3 lives here
__device__ int   g_deg[N_NODES];
__device__ int   g_off[N_NODES + 1];
__device__ int   g_cursor[N_NODES];
__device__ int   g_bsum[SCAN_BS];
__device__ int2  g_csr[N_EDGES];                   // {src, float bits of val}

// ---------------------------------------------------------------------------
// fp16 hi/lo split helpers
// ---------------------------------------------------------------------------
__device__ __forceinline__ uint32_t pack_split(float a, float b, uint32_t& lo) {
    const __half ha = __float2half_rn(a), hb = __float2half_rn(b);
    const __half la = __float2half_rn(a - __half2float(ha));
    const __half lb = __float2half_rn(b - __half2float(hb));
    const __half2 h = __halves2half2(ha, hb), l = __halves2half2(la, lb);
    lo = *reinterpret_cast<const uint32_t*>(&l);
    return *reinterpret_cast<const uint32_t*>(&h);
}

__device__ __forceinline__ void mma_f16(float* d, const uint32_t* a, uint32_t b0, uint32_t b1) {
    asm volatile(
        "mma.sync.aligned.m16n8k16.row.col.f32.f16.f16.f32 "
        "{%0,%1,%2,%3}, {%4,%5,%6,%7}, {%8,%9}, {%0,%1,%2,%3};"
        : "+f"(d[0]), "+f"(d[1]), "+f"(d[2]), "+f"(d[3])
        : "r"(a[0]), "r"(a[1]), "r"(a[2]), "r"(a[3]), "r"(b0), "r"(b1));
}

// ---------------------------------------------------------------------------
// Tensor-core GEMM (3-term fp16 split, fp32 accum): C[N,128] = (relu?)(A) @ W
// ---------------------------------------------------------------------------
#define SA_ST 20
#define SW_ST 136

template<int FIN, bool RELU>
__global__ __launch_bounds__(256, 2)
void gemm_hmma_kernel(const float* __restrict__ A,
                      const float* __restrict__ W,
                      __half* __restrict__ C) {
    __shared__ uint32_t sAh[128 * SA_ST];
    __shared__ uint32_t sAl[128 * SA_ST];
    __shared__ uint32_t sWh[16 * SW_ST];
    __shared__ uint32_t sWl[16 * SW_ST];

    const int tid  = threadIdx.x;
    const int lane = tid & 31;
    const int warp = tid >> 5;
    const int wm   = warp & 3;
    const int wn   = warp >> 2;
    const int g    = lane >> 2;
    const int tig  = lane & 3;
    const int row0 = blockIdx.x * 128;

    float acc[2][8][4];
    #pragma unroll
    for (int mf = 0; mf < 2; mf++)
        #pragma unroll
        for (int nf = 0; nf < 8; nf++)
            #pragma unroll
            for (int r = 0; r < 4; r++) acc[mf][nf][r] = 0.f;

    constexpr int NCHUNK = FIN / 32;
    for (int kc = 0; kc < NCHUNK; kc++) {
        #pragma unroll
        for (int j = 0; j < 4; j++) {
            const int idx = tid + 256 * j;
            const int r   = idx >> 3;
            const int c4  = (idx & 7) * 4;
            const int p0  = (idx & 7) * 2;
            const int gr  = min(row0 + r, N_NODES - 1);
            float4 v = __ldg(reinterpret_cast<const float4*>(A + (size_t)gr * FIN + kc * 32 + c4));
            if (RELU) {
                v.x = fmaxf(v.x, 0.f); v.y = fmaxf(v.y, 0.f);
                v.z = fmaxf(v.z, 0.f); v.w = fmaxf(v.w, 0.f);
            }
            uint32_t l0, l1;
            const uint32_t h0 = pack_split(v.x, v.y, l0);
            const uint32_t h1 = pack_split(v.z, v.w, l1);
            *reinterpret_cast<uint2*>(sAh + r * SA_ST + p0) = make_uint2(h0, h1);
            *reinterpret_cast<uint2*>(sAl + r * SA_ST + p0) = make_uint2(l0, l1);
        }
        #pragma unroll
        for (int j = 0; j < 4; j++) {
            const int idx = tid + 256 * j;
            const int p   = idx >> 6;
            const int c   = (idx & 63) * 2;
            const float2 v0 = __ldg(reinterpret_cast<const float2*>(W + (size_t)(kc * 32 + 2 * p) * 128 + c));
            const float2 v1 = __ldg(reinterpret_cast<const float2*>(W + (size_t)(kc * 32 + 2 * p + 1) * 128 + c));
            uint32_t l0, l1;
            const uint32_t h0 = pack_split(v0.x, v1.x, l0);
            const uint32_t h1 = pack_split(v0.y, v1.y, l1);
            *reinterpret_cast<uint2*>(sWh + p * SW_ST + c) = make_uint2(h0, h1);
            *reinterpret_cast<uint2*>(sWl + p * SW_ST + c) = make_uint2(l0, l1);
        }
        __syncthreads();

        #pragma unroll
        for (int ks = 0; ks < 2; ks++) {
            const int pb = ks * 8;
            uint32_t ah[2][4], al[2][4];
            #pragma unroll
            for (int mf = 0; mf < 2; mf++) {
                const int rb = wm * 32 + mf * 16 + g;
                ah[mf][0] = sAh[(rb)     * SA_ST + pb + tig];
                ah[mf][1] = sAh[(rb + 8) * SA_ST + pb + tig];
                ah[mf][2] = sAh[(rb)     * SA_ST + pb + tig + 4];
                ah[mf][3] = sAh[(rb + 8) * SA_ST + pb + tig + 4];
                al[mf][0] = sAl[(rb)     * SA_ST + pb + tig];
                al[mf][1] = sAl[(rb + 8) * SA_ST + pb + tig];
                al[mf][2] = sAl[(rb)     * SA_ST + pb + tig + 4];
                al[mf][3] = sAl[(rb + 8) * SA_ST + pb + tig + 4];
            }
            #pragma unroll
            for (int nf = 0; nf < 8; nf++) {
                const int col = wn * 64 + nf * 8 + g;
                const uint32_t bh0 = sWh[(pb + tig)     * SW_ST + col];
                const uint32_t bh1 = sWh[(pb + tig + 4) * SW_ST + col];
                const uint32_t bl0 = sWl[(pb + tig)     * SW_ST + col];
                const uint32_t bl1 = sWl[(pb + tig + 4) * SW_ST + col];
                #pragma unroll
                for (int mf = 0; mf < 2; mf++) {
                    mma_f16(acc[mf][nf], ah[mf], bh0, bh1);
                    mma_f16(acc[mf][nf], ah[mf], bl0, bl1);
                    mma_f16(acc[mf][nf], al[mf], bh0, bh1);
                }
            }
        }
        __syncthreads();
    }

    #pragma unroll
    for (int mf = 0; mf < 2; mf++) {
        const int r0 = row0 + wm * 32 + mf * 16 + g;
        const int r1 = r0 + 8;
        #pragma unroll
        for (int nf = 0; nf < 8; nf++) {
            const int c = wn * 64 + nf * 8 + tig * 2;
            if (r0 < N_NODES)
                *reinterpret_cast<__half2*>(C + (size_t)r0 * 128 + c) =
                    __floats2half2_rn(acc[mf][nf][0], acc[mf][nf][1]);
            if (r1 < N_NODES)
                *reinterpret_cast<__half2*>(C + (size_t)r1 * 128 + c) =
                    __floats2half2_rn(acc[mf][nf][2], acc[mf][nf][3]);
        }
    }
}

// ---------------------------------------------------------------------------
// Small GEMM for layer 3 (FOUT=40), fused ReLU on A, fp16 output.
// ---------------------------------------------------------------------------
template<int FIN, int FOUT, int G, int TR, bool RELU>
__global__ void gemm_small_kernel(const float* __restrict__ A,
                                  const float* __restrict__ W,
                                  __half* __restrict__ C) {
    constexpr int BM = G * TR;
    constexpr int NT = FOUT * G;
    __shared__ float sA[BM * FIN];

    const int col  = threadIdx.x;
    const int g    = threadIdx.y;
    const int row0 = blockIdx.x * BM;
    const int tid  = threadIdx.y * FOUT + threadIdx.x;

    const float4* A4  = reinterpret_cast<const float4*>(A + (size_t)row0 * FIN);
    float4*       sA4 = reinterpret_cast<float4*>(sA);
    constexpr int NV = BM * FIN / 4;
    for (int i = tid; i < NV; i += NT) {
        float4 v = __ldg(A4 + i);
        if (RELU) {
            v.x = fmaxf(v.x, 0.f); v.y = fmaxf(v.y, 0.f);
            v.z = fmaxf(v.z, 0.f); v.w = fmaxf(v.w, 0.f);
        }
        sA4[i] = v;
    }
    __syncthreads();

    float acc[TR];
    #pragma unroll
    for (int r = 0; r < TR; r++) acc[r] = 0.f;

    #pragma unroll 4
    for (int k = 0; k < FIN; k++) {
        const float w = __ldg(W + (size_t)k * FOUT + col);
        #pragma unroll
        for (int r = 0; r < TR; r++)
            acc[r] += sA[(g * TR + r) * FIN + k] * w;
    }

    #pragma unroll
    for (int r = 0; r < TR; r++)
        C[(size_t)(row0 + g * TR + r) * FOUT + col] = __float2half_rn(acc[r]);
}

// ---------------------------------------------------------------------------
// CSR build: histogram -> shuffle scans -> fill (packed int2)
// ---------------------------------------------------------------------------
__global__ void hist_kernel(const int* __restrict__ dst, int* __restrict__ deg) {
    const int e = blockIdx.x * blockDim.x + threadIdx.x;
    if (e < N_EDGES) atomicAdd(deg + __ldg(dst + e), 1);
}

__global__ void scan_block_kernel(const int* __restrict__ deg,
                                  int* __restrict__ off,
                                  int* __restrict__ bsum) {
    __shared__ int wsum[32];
    const int tid  = threadIdx.x;
    const int lane = tid & 31;
    const int wid  = tid >> 5;
    const int i    = blockIdx.x * SCAN_BS + tid;
    const int v    = (i < N_NODES) ? deg[i] : 0;

    int s = v;
    #pragma unroll
    for (int o = 1; o < 32; o <<= 1) {
        const int n = __shfl_up_sync(0xffffffffu, s, o);
        if (lane >= o) s += n;
    }
    if (lane == 31) wsum[wid] = s;
    __syncthreads();
    if (wid == 0) {
        int ws = wsum[lane];
        #pragma unroll
        for (int o = 1; o < 32; o <<= 1) {
            const int n = __shfl_up_sync(0xffffffffu, ws, o);
            if (lane >= o) ws += n;
        }
        wsum[lane] = ws;
    }
    __syncthreads();
    const int incl = s + (wid ? wsum[wid - 1] : 0);
    if (i < N_NODES) off[i] = incl - v;
    if (tid == SCAN_BS - 1) bsum[blockIdx.x] = incl;
}

__global__ void scan_sums_kernel(int* __restrict__ bsum) {
    __shared__ int wsum[4];
    const int tid  = threadIdx.x;
    const int lane = tid & 31;
    const int wid  = tid >> 5;
    const int v = (tid < NB) ? bsum[tid] : 0;
    int s = v;
    #pragma unroll
    for (int o = 1; o < 32; o <<= 1) {
        const int n = __shfl_up_sync(0xffffffffu, s, o);
        if (lane >= o) s += n;
    }
    if (lane == 31) wsum[wid] = s;
    __syncthreads();
    int add = 0;
    for (int w = 0; w < wid; w++) add += wsum[w];
    if (tid < NB) bsum[tid] = s + add - v;
}

__global__ void scan_add2_kernel(int* __restrict__ off,
                                 int* __restrict__ cursor,
                                 const int* __restrict__ bsum) {
    const int i = blockIdx.x * blockDim.x + threadIdx.x;
    if (i < N_NODES) {
        const int v = off[i] + __ldg(bsum + (i / SCAN_BS));
        off[i] = v;
        cursor[i] = v;
    }
    if (i == 0) off[N_NODES] = N_EDGES;
}

__global__ void csr_fill_kernel(const int* __restrict__ src,
                                const int* __restrict__ dst,
                                const float* __restrict__ evals,
                                int* __restrict__ cursor,
                                int2* __restrict__ csr) {
    const int e = blockIdx.x * blockDim.x + threadIdx.x;
    if (e >= N_EDGES) return;
    const int d = __ldg(dst + e);
    const int p = atomicAdd(cursor + d, 1);
    csr[p] = make_int2(__ldg(src + e), __float_as_int(__ldg(evals + e)));
}

// ---------------------------------------------------------------------------
// Pull-mode aggregation, fp16 support rows (256B), fp32 accumulate/output.
// ---------------------------------------------------------------------------
__global__ void gather128h_kernel(const __half* __restrict__ S,
                                  const int* __restrict__ off,
                                  const int2* __restrict__ csr,
                                  const float* __restrict__ bias,
                                  float* __restrict__ agg) {
    const int warp = threadIdx.x >> 5;
    const int lane = threadIdx.x & 31;
    const int d    = blockIdx.x * 8 + warp;
    if (d >= N_NODES) return;
    const int beg = __ldg(off + d);
    const int end = __ldg(off + d + 1);

    const uint2* S2 = reinterpret_cast<const uint2*>(S);
    float4 b = __ldg(reinterpret_cast<const float4*>(bias) + lane);
    float ax = b.x, ay = b.y, az = b.z, aw = b.w;

    int i = beg;
    for (; i + 8 <= end; i += 8) {
        int2 e[8];
        #pragma unroll
        for (int j = 0; j < 8; j++) e[j] = __ldg(csr + i + j);
        uint2 x[8];
        #pragma unroll
        for (int j = 0; j < 8; j++)
            x[j] = __ldcg(S2 + (size_t)e[j].x * 32 + lane);
        #pragma unroll
        for (int j = 0; j < 8; j++) {
            const float v = __int_as_float(e[j].y);
            const float2 f0 = __half22float2(*reinterpret_cast<const __half2*>(&x[j].x));
            const float2 f1 = __half22float2(*reinterpret_cast<const __half2*>(&x[j].y));
            ax += v * f0.x; ay += v * f0.y;
            az += v * f1.x; aw += v * f1.y;
        }
    }
    for (; i < end; i++) {
        const int2 e = __ldg(csr + i);
        const float v = __int_as_float(e.y);
        const uint2 x = __ldcg(S2 + (size_t)e.x * 32 + lane);
        const float2 f0 = __half22float2(*reinterpret_cast<const __half2*>(&x.x));
        const float2 f1 = __half22float2(*reinterpret_cast<const __half2*>(&x.y));
        ax += v * f0.x; ay += v * f0.y;
        az += v * f1.x; aw += v * f1.y;
    }
    reinterpret_cast<float4*>(agg)[(size_t)d * 32 + lane] = make_float4(ax, ay, az, aw);
}

// ---------------------------------------------------------------------------
// Fused gather (F=40, fp16 support) + log_softmax: one block (64 thr)/node.
// ---------------------------------------------------------------------------
__global__ void gather40h_softmax_kernel(const __half* __restrict__ S,
                                         const int* __restrict__ off,
                                         const int2* __restrict__ csr,
                                         const float* __restrict__ bias,
                                         float* __restrict__ out) {
    const int d = blockIdx.x;
    const int t = threadIdx.x;
    const float NEG_INF = __int_as_float(0xff800000);
    __shared__ float red[64];

    float acc = 0.f;
    if (t < NCLASS) {
        const int beg = __ldg(off + d);
        const int end = __ldg(off + d + 1);
        acc = __ldg(bias + t);
        int i = beg;
        for (; i + 8 <= end; i += 8) {
            int2 e[8];
            #pragma unroll
            for (int j = 0; j < 8; j++) e[j] = __ldg(csr + i + j);
            float x[8];
            #pragma unroll
            for (int j = 0; j < 8; j++)
                x[j] = __half2float(__ldcg(S + (size_t)e[j].x * NCLASS + t));
            #pragma unroll
            for (int j = 0; j < 8; j++)
                acc += __int_as_float(e[j].y) * x[j];
        }
        for (; i < end; i++) {
            const int2 e = __ldg(csr + i);
            acc += __int_as_float(e.y) * __half2float(__ldcg(S + (size_t)e.x * NCLASS + t));
        }
    }

    red[t] = (t < NCLASS) ? acc : NEG_INF;
    __syncthreads();
    if (t < 32) {
        float x = fmaxf(red[t], red[t + 32]);
        #pragma unroll
        for (int o = 16; o; o >>= 1) x = fmaxf(x, __shfl_xor_sync(0xffffffffu, x, o));
        if (t == 0) red[0] = x;
    }
    __syncthreads();
    const float m = red[0];
    __syncthreads();

    red[t] = (t < NCLASS) ? expf(acc - m) : 0.f;
    __syncthreads();
    if (t < 32) {
        float x = red[t] + red[t + 32];
        #pragma unroll
        for (int o = 16; o; o >>= 1) x += __shfl_xor_sync(0xffffffffu, x, o);
        if (t == 0) red[0] = x;
    }
    __syncthreads();
    const float ls = m + logf(red[0]);

    if (t < NCLASS) out[(size_t)d * NCLASS + t] = acc - ls;
}

// ---------------------------------------------------------------------------
extern "C" void kernel_launch(void* const* d_in, const int* in_sizes, int n_in,
                              void* d_out, int out_size) {
    const float* x    = (const float*)d_in[0];
    const int*   esrc = (const int*)  d_in[1];
    const int*   edst = (const int*)  d_in[2];
    const float* ev   = (const float*)d_in[3];
    const float* W1   = (const float*)d_in[4];
    const float* b1   = (const float*)d_in[5];
    const float* W2   = (const float*)d_in[6];
    const float* b2   = (const float*)d_in[7];
    const float* W3   = (const float*)d_in[8];
    const float* b3   = (const float*)d_in[9];
    float* out = (float*)d_out;

    float *bufA, *bufB, *bufC;
    int *deg, *off, *cursor, *bsum;
    int2 *csr;
    cudaGetSymbolAddress((void**)&bufA,   g_bufA);
    cudaGetSymbolAddress((void**)&bufB,   g_bufB);
    cudaGetSymbolAddress((void**)&bufC,   g_bufC);
    cudaGetSymbolAddress((void**)&deg,    g_deg);
    cudaGetSymbolAddress((void**)&off,    g_off);
    cudaGetSymbolAddress((void**)&cursor, g_cursor);
    cudaGetSymbolAddress((void**)&bsum,   g_bsum);
    cudaGetSymbolAddress((void**)&csr,    g_csr);
    __half* bufAh = reinterpret_cast<__half*>(bufA);
    __half* bufCh = reinterpret_cast<__half*>(bufC);

    const int edge_blocks   = (N_EDGES + 255) / 256;
    const int gemm_blocks   = (N_NODES + 127) / 128;
    const int gather_blocks = (N_NODES + 7) / 8;

    // ---- Fork: CSR build on side stream, GEMM1 on main (legacy) stream ----
    cudaStream_t s2;
    cudaEvent_t evFork, evJoin;
    cudaStreamCreateWithFlags(&s2, cudaStreamNonBlocking);
    cudaEventCreateWithFlags(&evFork, cudaEventDisableTiming);
    cudaEventCreateWithFlags(&evJoin, cudaEventDisableTiming);

    cudaEventRecord(evFork, 0);
    cudaStreamWaitEvent(s2, evFork, 0);

    // CSR chain on s2 (touches only edge arrays)
    cudaMemsetAsync(deg, 0, N_NODES * sizeof(int), s2);
    hist_kernel<<<edge_blocks, 256, 0, s2>>>(edst, deg);
    scan_block_kernel<<<NB, SCAN_BS, 0, s2>>>(deg, off, bsum);
    scan_sums_kernel<<<1, 128, 0, s2>>>(bsum);
    scan_add2_kernel<<<(N_NODES + 255) / 256, 256, 0, s2>>>(off, cursor, bsum);
    csr_fill_kernel<<<edge_blocks, 256, 0, s2>>>(esrc, edst, ev, cursor, csr);
    cudaEventRecord(evJoin, s2);

    // GEMM1 on main stream (touches only x, W1)
    gemm_hmma_kernel<NFEAT, false><<<gemm_blocks, 256>>>(x, W1, bufAh);

    // Join: gathers need the CSR
    cudaStreamWaitEvent(0, evJoin, 0);

    // ---- Layer 1 aggregation ----
    gather128h_kernel<<<gather_blocks, 256>>>(bufAh, off, csr, b1, bufB);

    // ---- Layer 2 ----
    gemm_hmma_kernel<NHID, true><<<gemm_blocks, 256>>>(bufB, W2, bufAh);
    gather128h_kernel<<<gather_blocks, 256>>>(bufAh, off, csr, b2, bufB);

    // ---- Layer 3 (fp16 support, fused softmax) ----
    gemm_small_kernel<NHID, NCLASS, 8, 2, true><<<N_NODES / 16, dim3(NCLASS, 8)>>>(bufB, W3, bufCh);
    gather40h_softmax_kernel<<<N_NODES, 64>>>(bufCh, off, csr, b3, out);

    cudaEventDestroy(evFork);
    cudaEventDestroy(evJoin);
    cudaStreamDestroy(s2);
}